// round 12
// baseline (speedup 1.0000x reference)
#include <cuda_runtime.h>

#define NCLS 19
#define CH   32
#define IN_H 128
#define IN_W 128
#define OUT_H 512
#define OUT_W 512
#define NB   4
#define HB   16
#define TPAD 67   // tile column pad (67%32=3, coprime -> conflict-free)

__device__ float    g_S1[NB * NCLS * CH];
__device__ float    g_S2[NB * NCLS * CH];
__device__ int      g_hist[NB][HB][NCLS];
__device__ unsigned g_done;

// ---------------------------------------------------------------------------
// Histogram + accumulator zeroing.
__global__ void __launch_bounds__(256) hist_kernel(const int* __restrict__ label) {
    __shared__ int whist[8][NCLS];
    const int n   = blockIdx.x >> 4;
    const int h   = blockIdx.x & 15;
    const int tid = threadIdx.x;
    const int w   = tid >> 5;
    const int lane = tid & 31;

    if (blockIdx.x == 0) {
        for (int i = tid; i < NB * NCLS * CH; i += 256) { g_S1[i] = 0.f; g_S2[i] = 0.f; }
        if (tid == 0) g_done = 0u;
    }

    for (int i = lane; i < NCLS; i += 32) whist[w][i] = 0;
    __syncwarp();

    const int4* lp = (const int4*)(label + (size_t)n * OUT_H * OUT_W
                                         + (size_t)h * (OUT_H * OUT_W / HB));
    #pragma unroll
    for (int r = 0; r < 16; ++r) {
        int4 L = lp[r * 256 + tid];
        int ks[4] = {L.x, L.y, L.z, L.w};
        #pragma unroll
        for (int j = 0; j < 4; ++j) {
            int k = (int)min((unsigned)ks[j], (unsigned)(NCLS - 1));
            unsigned m = __match_any_sync(0xffffffffu, k);
            if (lane == (__ffs(m) - 1)) whist[w][k] += __popc(m);
        }
    }
    __syncthreads();
    if (tid < NCLS) {
        int c = 0;
        #pragma unroll
        for (int ww = 0; ww < 8; ++ww) c += whist[ww][tid];
        g_hist[n][h][tid] = c;
    }
}

// ---------------------------------------------------------------------------
// Main: CTA = 128 threads (4 warps), warp = half of output row y = 4q+w.
// TWO disjoint bin arrays per warp (even/odd groups) -> two independent
// RMW chains in flight -> half the exposed serial smem latency per group.
__global__ void __launch_bounds__(128) main_kernel(const float* __restrict__ emb,
                                                   const int*   __restrict__ label,
                                                   float* __restrict__ out) {
    __shared__ float    tile[3][CH][TPAD];                          // 25728 B
    __shared__ __align__(16) unsigned char rawE[4 * NCLS * CH * 8]; // 19456 B
    __shared__ __align__(16) unsigned char rawO[4 * NCLS * CH * 8]; // 19456 B
    __shared__ unsigned slab[4][64];                                // 1024 B
    __shared__ unsigned s_last;
    float2 (*sE)[NCLS * CH] = reinterpret_cast<float2 (*)[NCLS * CH]>(rawE);
    float2 (*sO)[NCLS * CH] = reinterpret_cast<float2 (*)[NCLS * CH]>(rawO);

    const int tid  = threadIdx.x;
    const int w    = tid >> 5;
    const int lane = tid & 31;
    const int bx   = blockIdx.x;
    const int n    = bx >> 8;            // 4 batches
    const int q    = (bx >> 1) & 127;    // 128 row-quads
    const int half = bx & 1;
    const int y    = 4 * q + w;
    const int g0   = half * 64;          // first input column group

    // ---- stage labels (packed 4x8bit per group word) ----
    {
        const int4* lp = (const int4*)(label + ((size_t)(n * OUT_H + y) * OUT_W)) + g0;
        int4 L0 = lp[lane];
        int4 L1 = lp[lane + 32];
        slab[w][lane]      = (unsigned)L0.x | ((unsigned)L0.y << 8) |
                             ((unsigned)L0.z << 16) | ((unsigned)L0.w << 24);
        slab[w][lane + 32] = (unsigned)L1.x | ((unsigned)L1.y << 8) |
                             ((unsigned)L1.z << 16) | ((unsigned)L1.w << 24);
    }

    // ---- load embedding tile: rows q-1,q,q+1 (clamped), cols g0-1..g0+64 ----
    {
        const float* eb = emb + (size_t)n * CH * IN_H * IN_W;
        for (int idx = tid; idx < 3 * CH * 66; idx += 128) {
            int rr  = idx / (CH * 66);
            int rem = idx - rr * (CH * 66);
            int c   = rem / 66;
            int i   = rem - c * 66;
            int row = q - 1 + rr; row = row < 0 ? 0 : (row > IN_H - 1 ? IN_H - 1 : row);
            int col = g0 - 1 + i; col = col < 0 ? 0 : (col > IN_W - 1 ? IN_W - 1 : col);
            tile[rr][c][i] = __ldg(&eb[((size_t)c * IN_H + row) * IN_W + col]);
        }
    }

    // ---- zero bins ----
    for (int i = tid; i < 4 * NCLS * CH / 2; i += 128) {
        ((float4*)rawE)[i] = make_float4(0.f, 0.f, 0.f, 0.f);
        ((float4*)rawO)[i] = make_float4(0.f, 0.f, 0.f, 0.f);
    }
    __syncthreads();

    // ---- hot loop (pure smem, dual chains) ----
    const float fy = 0.125f + 0.25f * (float)((y + 2) & 3);
    const int   rA = w >> 1;             // w=0,1 -> rows(0,1); w=2,3 -> rows(1,2)
    const float* tAp = &tile[rA][lane][0];
    const float* tBp = &tile[rA + 1][lane][0];
    float2* __restrict__ sblE = sE[w] + lane;
    float2* __restrict__ sblO = sO[w] + lane;

    auto binTo = [&](float2* base, int k, float v) {
        float2* p = base + k * CH;
        float2 o = *p;
        o.x += v;
        o.y = fmaf(v, v, o.y);
        *p = o;
    };

    float a0 = tAp[0], b0 = tBp[0];
    float yvA = fmaf(fy, b0 - a0, a0);   // column g0-1 (clamped)
    float a1 = tAp[1], b1 = tBp[1];
    float yvB = fmaf(fy, b1 - a1, a1);   // column g0

    #pragma unroll 2
    for (int t = 0; t < 64; t += 2) {
        // even group t -> binsE
        {
            float a = tAp[t + 2], b = tBp[t + 2];
            float yvC = fmaf(fy, b - a, a);
            unsigned Lp = slab[w][t];
            float d0 = yvB - yvA;
            float d1 = yvC - yvB;
            binTo(sblE, (int)(Lp & 0xffu),         fmaf(0.625f, d0, yvA));
            binTo(sblE, (int)((Lp >> 8) & 0xffu),  fmaf(0.875f, d0, yvA));
            binTo(sblE, (int)((Lp >> 16) & 0xffu), fmaf(0.125f, d1, yvB));
            binTo(sblE, (int)(Lp >> 24),           fmaf(0.375f, d1, yvB));
            yvA = yvB; yvB = yvC;
        }
        // odd group t+1 -> binsO (independent chain)
        {
            float a = tAp[t + 3], b = tBp[t + 3];
            float yvC = fmaf(fy, b - a, a);
            unsigned Lp = slab[w][t + 1];
            float d0 = yvB - yvA;
            float d1 = yvC - yvB;
            binTo(sblO, (int)(Lp & 0xffu),         fmaf(0.625f, d0, yvA));
            binTo(sblO, (int)((Lp >> 8) & 0xffu),  fmaf(0.875f, d0, yvA));
            binTo(sblO, (int)((Lp >> 16) & 0xffu), fmaf(0.125f, d1, yvB));
            binTo(sblO, (int)(Lp >> 24),           fmaf(0.375f, d1, yvB));
            yvA = yvB; yvB = yvC;
        }
    }
    __syncthreads();

    // ---- reduce 4 warps x 2 arrays -> global atomics ----
    for (int i = tid; i < NCLS * CH; i += 128) {
        float a = 0.f, b = 0.f;
        #pragma unroll
        for (int ww = 0; ww < 4; ++ww) {
            float2 vE = sE[ww][i]; a += vE.x; b += vE.y;
            float2 vO = sO[ww][i]; a += vO.x; b += vO.y;
        }
        atomicAdd(&g_S1[n * NCLS * CH + i], a);
        atomicAdd(&g_S2[n * NCLS * CH + i], b);
    }

    __threadfence();
    if (tid == 0) s_last = (atomicAdd(&g_done, 1u) == (unsigned)(gridDim.x - 1));
    __syncthreads();
    if (!s_last) return;

    // ---------------- epilogue (last CTA, reuses bin smem) ----------------
    struct Epi {
        float cnt[NB][NCLS];
        float mu[NB][NCLS][CH];
        float intra[NB][NCLS];
        float inter[NB];
        float nfg[NB];
        float l2i[NB];
    };
    Epi* e = reinterpret_cast<Epi*>(rawE);
    __syncthreads();

    if (tid < NB * NCLS) {
        int nn = tid / NCLS, k = tid % NCLS;
        int c = 0;
        #pragma unroll
        for (int h = 0; h < HB; ++h) c += g_hist[nn][h][k];
        e->cnt[nn][k] = (float)c;
    }
    __syncthreads();

    {   // warp w = batch w: per-class mean + intra
        for (int k = 0; k < NCLS; ++k) {
            float cn = e->cnt[w][k];
            float s1 = __ldcg(&g_S1[w * NCLS * CH + k * CH + lane]);
            float s2 = __ldcg(&g_S2[w * NCLS * CH + k * CH + lane]);
            float m  = s1 / (cn + 1.0f);
            e->mu[w][k][lane] = m;
            float t2 = s2 + m * fmaf(cn, m, -2.0f * s1);
            #pragma unroll
            for (int o = 16; o; o >>= 1) t2 += __shfl_xor_sync(0xffffffffu, t2, o);
            if (lane == 0) e->intra[w][k] = t2 / ((float)CH * (cn + 1.0f));
        }
    }
    __syncthreads();

    if (tid < NB) {
        float nf = 0.f, li = 0.f;
        for (int k = 1; k < NCLS; ++k)
            if (e->cnt[tid][k] > 0.f) { nf += 1.f; li += e->intra[tid][k]; }
        e->nfg[tid] = nf;
        e->l2i[tid] = li / nf;
    }
    __syncthreads();

    {   // warp w = batch w: inter-class pairwise distances
        float acc = 0.f;
        for (int j = 1; j < NCLS; ++j) {
            if (e->cnt[w][j] <= 0.f) continue;
            float mj = e->mu[w][j][lane];
            for (int k = 1; k < NCLS; ++k) {
                if (e->cnt[w][k] > 0.f) {
                    float d = mj - e->mu[w][k][lane];
                    acc = fmaf(d, d, acc);
                }
            }
        }
        #pragma unroll
        for (int o = 16; o; o >>= 1) acc += __shfl_xor_sync(0xffffffffu, acc, o);
        if (lane == 0) e->inter[w] = acc / (float)CH;
    }
    __syncthreads();

    if (tid < NB)
        out[tid] = e->l2i[tid] - e->inter[tid] / (e->nfg[tid] * e->nfg[tid]);
}

// ---------------------------------------------------------------------------
extern "C" void kernel_launch(void* const* d_in, const int* in_sizes, int n_in,
                              void* d_out, int out_size) {
    const float* emb   = (const float*)d_in[0];   // (4,32,128,128) f32
    const int*   label = (const int*)d_in[1];     // (4,512,512) int32
    float*       out   = (float*)d_out;           // (4,) f32

    hist_kernel<<<NB * HB, 256>>>(label);
    main_kernel<<<NB * 128 * 2, 128>>>(emb, label, out);
}

// round 13
// speedup vs baseline: 1.1317x; 1.1317x over previous
#include <cuda_runtime.h>

#define NCLS 19
#define CH   32
#define IN_H 128
#define IN_W 128
#define OUT_H 512
#define OUT_W 512
#define NB   4
#define HB   16
#define GRID_MAIN (NB * 64 * 2)   // 512
#define GRID_PREP (NB * IN_H + NB * HB)  // 512 transpose + 64 hist

__device__ float    g_T[(size_t)NB * IN_H * IN_W * CH];  // (N,H,W,C)
__device__ float    g_S1[NB * NCLS * CH];
__device__ float    g_S2[NB * NCLS * CH];
__device__ int      g_hist[NB][HB][NCLS];
__device__ unsigned g_done;

// ---------------------------------------------------------------------------
// Prep (one launch): blocks [0,512) transpose one row-strip each;
// blocks [512,576) build label histograms; block 512 zeroes accumulators.
__global__ void __launch_bounds__(256) prep_kernel(const float* __restrict__ in,
                                                   const int* __restrict__ label) {
    const int tid = threadIdx.x;
    const int bx  = blockIdx.x;

    if (bx < NB * IN_H) {
        // ---- transpose row strip: emb[n][c][y][:] -> g_T[n][y][:][c] ----
        __shared__ float tmp[CH][IN_W + 1];   // pad 129 words: conflict-free
        const int n = bx >> 7;
        const int y = bx & 127;
        const float* src = in + ((size_t)n * CH * IN_H + y) * IN_W;
        #pragma unroll
        for (int i = tid; i < CH * IN_W; i += 256) {
            int c = i >> 7;            // i / 128
            int x = i & 127;
            tmp[c][x] = src[(size_t)c * IN_H * IN_W + x];   // coalesced in x
        }
        __syncthreads();
        float* dst = g_T + ((size_t)n * IN_H + y) * IN_W * CH;
        #pragma unroll
        for (int i = tid; i < CH * IN_W; i += 256) {
            int x = i >> 5;            // i / 32
            int c = i & 31;
            dst[i] = tmp[c][x];        // coalesced write; banks (c+x)%32 distinct
        }
    } else {
        // ---- histogram blocks ----
        __shared__ int whist[8][NCLS];
        const int hb  = bx - NB * IN_H;
        const int n   = hb >> 4;
        const int h   = hb & 15;
        const int w   = tid >> 5;
        const int lane = tid & 31;

        if (hb == 0) {
            for (int i = tid; i < NB * NCLS * CH; i += 256) { g_S1[i] = 0.f; g_S2[i] = 0.f; }
            if (tid == 0) g_done = 0u;
        }

        for (int i = lane; i < NCLS; i += 32) whist[w][i] = 0;
        __syncwarp();

        const int4* lp = (const int4*)(label + (size_t)n * OUT_H * OUT_W
                                             + (size_t)h * (OUT_H * OUT_W / HB));
        #pragma unroll
        for (int r = 0; r < 16; ++r) {
            int4 L = lp[r * 256 + tid];
            int ks[4] = {L.x, L.y, L.z, L.w};
            #pragma unroll
            for (int j = 0; j < 4; ++j) {
                int k = (int)min((unsigned)ks[j], (unsigned)(NCLS - 1));
                unsigned m = __match_any_sync(0xffffffffu, k);
                if (lane == (__ffs(m) - 1)) whist[w][k] += __popc(m);
            }
        }
        __syncthreads();
        if (tid < NCLS) {
            int c = 0;
            #pragma unroll
            for (int ww = 0; ww < 8; ++ww) c += whist[ww][tid];
            g_hist[n][h][tid] = c;
        }
    }
}

// ---------------------------------------------------------------------------
// Main pass (R8 proven config): warp = half an output row, lane = channel.
__global__ void __launch_bounds__(256) main_kernel(const int* __restrict__ label,
                                                   float* __restrict__ out) {
    __shared__ __align__(16) unsigned char raw[8 * NCLS * CH * 8];  // 38912 B
    __shared__ __align__(16) int4 slab[8][64];                      // 8192 B labels
    float2 (*s)[NCLS * CH] = reinterpret_cast<float2 (*)[NCLS * CH]>(raw);
    __shared__ unsigned s_last;

    const int tid  = threadIdx.x;
    const int w    = tid >> 5;
    const int lane = tid & 31;
    const int bx   = blockIdx.x;
    const int n    = bx >> 7;            // 4 batches
    const int rem  = bx & 127;
    const int rb   = rem >> 1;           // 64 row-blocks
    const int half = rem & 1;            // left / right half of the row
    const int y    = rb * 8 + w;         // warp's output row
    const int g0   = half * 64;          // first 4-px group of this warp

    // stage this warp's 256 labels into smem (2 coalesced LDG.128 per lane)
    {
        const int4* lp = (const int4*)(label + ((size_t)(n * OUT_H + y) * OUT_W)) + g0;
        slab[w][lane]      = lp[lane];
        slab[w][lane + 32] = lp[lane + 32];
    }

    for (int i = tid; i < 8 * NCLS * CH / 2; i += 256)
        ((float4*)raw)[i] = make_float4(0.f, 0.f, 0.f, 0.f);
    __syncthreads();

    // y interpolation (scale exactly 4, half-pixel sampling)
    const int   y0  = ((y + 2) >> 2) - 1;
    const float fy  = 0.125f + 0.25f * (float)((y + 2) & 3);
    const int   y0c = y0 < 0 ? 0 : y0;
    const int   y1c = (y0 + 1) > (IN_H - 1) ? (IN_H - 1) : (y0 + 1);

    const float* __restrict__ rowA = g_T + ((size_t)(n * IN_H + y0c) * IN_W) * CH + lane;
    const float* __restrict__ rowB = g_T + ((size_t)(n * IN_H + y1c) * IN_W) * CH + lane;

    float2* __restrict__ sbl = s[w] + lane;

    auto bin = [&](int k, float v) {                 // k trusted in [0,19)
        float2* p = sbl + k * CH;
        float2 o = *p;
        o.x += v;
        o.y = fmaf(v, v, o.y);
        *p = o;
    };

    // prologue: yvB = column g0; yvA = column g0-1 (clamped for half 0)
    const float* pA = rowA + g0 * CH;
    const float* pB = rowB + g0 * CH;
    float a0 = pA[0], b0 = pB[0];
    float yvB = fmaf(fy, b0 - a0, a0);
    float yvA;
    if (half) {
        float a1 = pA[-CH], b1 = pB[-CH];
        yvA = fmaf(fy, b1 - a1, a1);
    } else {
        yvA = yvB;                        // column -1 clamps to column 0
    }
    pA += CH; pB += CH;                   // now at column g0+1 (first yvC)

    // 63 clean groups (rel t = 0..62)
    #pragma unroll 4
    for (int t = 0; t < 63; ++t) {
        float a = pA[0], b = pB[0];
        pA += CH; pB += CH;
        float yvC = fmaf(fy, b - a, a);
        int4  L   = slab[w][t];
        float d0  = yvB - yvA;
        float d1  = yvC - yvB;
        bin(L.x, fmaf(0.625f, d0, yvA));
        bin(L.y, fmaf(0.875f, d0, yvA));
        bin(L.z, fmaf(0.125f, d1, yvB));
        bin(L.w, fmaf(0.375f, d1, yvB));
        yvA = yvB; yvB = yvC;
    }
    {   // final group (rel t = 63): half 0 loads col 64; half 1 clamps col 128
        float yvC;
        if (!half) {
            float a = pA[0], b = pB[0];
            yvC = fmaf(fy, b - a, a);
        } else {
            yvC = yvB;
        }
        int4  L  = slab[w][63];
        float d0 = yvB - yvA;
        float d1 = yvC - yvB;
        bin(L.x, fmaf(0.625f, d0, yvA));
        bin(L.y, fmaf(0.875f, d0, yvA));
        bin(L.z, fmaf(0.125f, d1, yvB));
        bin(L.w, fmaf(0.375f, d1, yvB));
    }
    __syncthreads();

    // reduce 8 warp copies -> global atomics
    for (int i = tid; i < NCLS * CH; i += 256) {
        float a = 0.f, b = 0.f;
        #pragma unroll
        for (int ww = 0; ww < 8; ++ww) { float2 v = s[ww][i]; a += v.x; b += v.y; }
        atomicAdd(&g_S1[n * NCLS * CH + i], a);
        atomicAdd(&g_S2[n * NCLS * CH + i], b);
    }

    __threadfence();
    if (tid == 0) s_last = (atomicAdd(&g_done, 1u) == (unsigned)(gridDim.x - 1));
    __syncthreads();
    if (!s_last) return;

    // ---------------- epilogue (last CTA, reuses smem) ----------------
    struct Epi {
        float cnt[NB][NCLS];
        float mu[NB][NCLS][CH];
        float intra[NB][NCLS];
        float interp[NB][2];
        float nfg[NB];
        float l2i[NB];
    };
    Epi* e = reinterpret_cast<Epi*>(raw);
    __syncthreads();

    if (tid < NB * NCLS) {
        int nn = tid / NCLS, k = tid % NCLS;
        int c = 0;
        #pragma unroll
        for (int h = 0; h < HB; ++h) c += g_hist[nn][h][k];
        e->cnt[nn][k] = (float)c;
    }
    __syncthreads();

    {   // per-class mean + intra (warp pair per batch)
        int nn = w >> 1, sub = w & 1;
        for (int k = sub; k < NCLS; k += 2) {
            float cn = e->cnt[nn][k];
            float s1 = __ldcg(&g_S1[nn * NCLS * CH + k * CH + lane]);
            float s2 = __ldcg(&g_S2[nn * NCLS * CH + k * CH + lane]);
            float m  = s1 / (cn + 1.0f);
            e->mu[nn][k][lane] = m;
            float t2 = s2 + m * fmaf(cn, m, -2.0f * s1);
            #pragma unroll
            for (int o = 16; o; o >>= 1) t2 += __shfl_xor_sync(0xffffffffu, t2, o);
            if (lane == 0) e->intra[nn][k] = t2 / ((float)CH * (cn + 1.0f));
        }
    }
    __syncthreads();

    if (tid < NB) {
        float nf = 0.f, li = 0.f;
        for (int k = 1; k < NCLS; ++k)
            if (e->cnt[tid][k] > 0.f) { nf += 1.f; li += e->intra[tid][k]; }
        e->nfg[tid] = nf;
        e->l2i[tid] = li / nf;
    }
    __syncthreads();

    {   // inter: masked pairwise mean-squared distances
        int nn = w >> 1, sub = w & 1;
        float acc = 0.f;
        for (int p = sub; p < NCLS * NCLS; p += 2) {
            int j = p / NCLS, k = p - j * NCLS;
            if (j >= 1 && k >= 1 && e->cnt[nn][j] > 0.f && e->cnt[nn][k] > 0.f) {
                float d = e->mu[nn][j][lane] - e->mu[nn][k][lane];
                acc = fmaf(d, d, acc);
            }
        }
        #pragma unroll
        for (int o = 16; o; o >>= 1) acc += __shfl_xor_sync(0xffffffffu, acc, o);
        if (lane == 0) e->interp[nn][sub] = acc / (float)CH;
    }
    __syncthreads();

    if (tid < NB) {
        float inter = e->interp[tid][0] + e->interp[tid][1];
        out[tid] = e->l2i[tid] - inter / (e->nfg[tid] * e->nfg[tid]);
    }
}

// ---------------------------------------------------------------------------
extern "C" void kernel_launch(void* const* d_in, const int* in_sizes, int n_in,
                              void* d_out, int out_size) {
    const float* emb   = (const float*)d_in[0];   // (4,32,128,128) f32
    const int*   label = (const int*)d_in[1];     // (4,512,512) int32
    float*       out   = (float*)d_out;           // (4,) f32

    prep_kernel<<<GRID_PREP, 256>>>(emb, label);
    main_kernel<<<GRID_MAIN, 256>>>(label, out);
}

// round 14
// speedup vs baseline: 1.2563x; 1.1101x over previous
#include <cuda_runtime.h>

#define NCLS 19
#define CH   32
#define IN_H 128
#define IN_W 128
#define OUT_H 512
#define OUT_W 512
#define NB   4
#define TPAD 67   // tile col stride: (67c+x)%32=(3c+x)%32 -> conflict-free

__device__ float    g_S1[NB * NCLS * CH];   // zero-init at load; self-cleaned
__device__ float    g_S2[NB * NCLS * CH];
__device__ int      g_cnt[NB * NCLS];
__device__ unsigned g_done;

// ---------------------------------------------------------------------------
// Fully fused: tile load + bilinear scatter + histogram + reduce + epilogue.
// CTA = 128 threads (4 warps); warp w = row y=4q+w, half-row (256 px).
__global__ void __launch_bounds__(128) main_kernel(const float* __restrict__ emb,
                                                   const int*   __restrict__ label,
                                                   float* __restrict__ out) {
    __shared__ float    tile[3][CH][TPAD];                          // 25728 B
    __shared__ __align__(16) unsigned char raw[4 * NCLS * CH * 8];  // 19456 B
    __shared__ unsigned slab[4][64];                                // 1024 B
    __shared__ int      whist[4][NCLS];
    __shared__ unsigned s_last;
    float2 (*s)[NCLS * CH] = reinterpret_cast<float2 (*)[NCLS * CH]>(raw);

    const int tid  = threadIdx.x;
    const int w    = tid >> 5;
    const int lane = tid & 31;
    const int bx   = blockIdx.x;
    const int n    = bx >> 8;            // 4 batches
    const int q    = (bx >> 1) & 127;    // 128 row-quads
    const int half = bx & 1;
    const int y    = 4 * q + w;
    const int g0   = half * 64;          // first input column of this half

    // ---- stage labels (packed 4x8bit per group word) ----
    {
        const int4* lp = (const int4*)(label + ((size_t)(n * OUT_H + y) * OUT_W)) + g0;
        int4 L0 = lp[lane];
        int4 L1 = lp[lane + 32];
        slab[w][lane]      = (unsigned)L0.x | ((unsigned)L0.y << 8) |
                             ((unsigned)L0.z << 16) | ((unsigned)L0.w << 24);
        slab[w][lane + 32] = (unsigned)L1.x | ((unsigned)L1.y << 8) |
                             ((unsigned)L1.z << 16) | ((unsigned)L1.w << 24);
        for (int i = lane; i < NCLS; i += 32) whist[w][i] = 0;
    }

    // ---- tile load: rows q-1,q,q+1 (clamped), cols g0-1 .. g0+64 ----
    // layout: idx 0 = col g0-1 (clamped); idx 1+j = col g0+j; idx 65 = col g0+64 (clamped)
    {
        const int sgrp = w;              // col chunk 0..3 (16 cols each)
        const float* eb = emb + (size_t)n * (CH * IN_H * IN_W);
        #pragma unroll
        for (int rr = 0; rr < 3; ++rr) {
            int row = q - 1 + rr;
            row = row < 0 ? 0 : (row > IN_H - 1 ? IN_H - 1 : row);
            const float* srcr = eb + ((size_t)lane * IN_H + row) * IN_W;
            const float4* src = (const float4*)(srcr + g0 + 16 * sgrp);
            float* dr = &tile[rr][lane][0];
            #pragma unroll
            for (int i = 0; i < 4; ++i) {
                float4 v = src[i];
                int x = 1 + 16 * sgrp + 4 * i;
                dr[x] = v.x; dr[x + 1] = v.y; dr[x + 2] = v.z; dr[x + 3] = v.w;
            }
            if (sgrp == 0) {
                int colL = g0 - 1; colL = colL < 0 ? 0 : colL;
                dr[0] = srcr[colL];
            } else if (sgrp == 1) {
                int colR = g0 + 64; colR = colR > IN_W - 1 ? IN_W - 1 : colR;
                dr[65] = srcr[colR];
            }
        }
    }

    // ---- zero bins ----
    for (int i = tid; i < 4 * NCLS * CH / 2; i += 128)
        ((float4*)raw)[i] = make_float4(0.f, 0.f, 0.f, 0.f);
    __syncthreads();

    // ---- hot loop (branch-free, pure smem) ----
    const float fy = 0.125f + 0.25f * (float)((y + 2) & 3);
    const int   rA = w >> 1;             // w=0,1 -> rows(0,1); w=2,3 -> rows(1,2)
    const float* tAp = &tile[rA][lane][0];
    const float* tBp = &tile[rA + 1][lane][0];
    float2* __restrict__ sbl = s[w] + lane;

    auto bin = [&](int k, float v) {
        float2* p = sbl + k * CH;
        float2 o = *p;
        o.x += v;
        o.y = fmaf(v, v, o.y);
        *p = o;
    };

    float a0 = tAp[0], b0 = tBp[0];
    float yvA = fmaf(fy, b0 - a0, a0);   // col g0-1 (clamped at load)
    float a1 = tAp[1], b1 = tBp[1];
    float yvB = fmaf(fy, b1 - a1, a1);   // col g0

    #pragma unroll 4
    for (int t = 0; t < 64; ++t) {
        float a = tAp[t + 2], b = tBp[t + 2];   // col g0+t+1 (edge preclamped)
        float yvC = fmaf(fy, b - a, a);
        unsigned Lp = slab[w][t];
        float d0 = yvB - yvA;
        float d1 = yvC - yvB;
        bin((int)(Lp & 0xffu),         fmaf(0.625f, d0, yvA));
        bin((int)((Lp >> 8) & 0xffu),  fmaf(0.875f, d0, yvA));
        bin((int)((Lp >> 16) & 0xffu), fmaf(0.125f, d1, yvB));
        bin((int)(Lp >> 24),           fmaf(0.375f, d1, yvB));
        yvA = yvB; yvB = yvC;
    }

    // ---- fused histogram: warp counts its own 256 staged labels ----
    #pragma unroll
    for (int it = 0; it < 8; ++it) {
        unsigned word = slab[w][it * 8 + (lane >> 2)];
        int k = (int)((word >> ((lane & 3) * 8)) & 0xffu);
        unsigned m = __match_any_sync(0xffffffffu, k);
        if (lane == (__ffs(m) - 1)) whist[w][k] += __popc(m);
    }
    __syncthreads();

    // ---- reduce 4 warp copies -> global atomics ----
    for (int i = tid; i < NCLS * CH; i += 128) {
        float a = 0.f, b = 0.f;
        #pragma unroll
        for (int ww = 0; ww < 4; ++ww) { float2 v = s[ww][i]; a += v.x; b += v.y; }
        atomicAdd(&g_S1[n * NCLS * CH + i], a);
        atomicAdd(&g_S2[n * NCLS * CH + i], b);
    }
    if (tid < NCLS) {
        int c = whist[0][tid] + whist[1][tid] + whist[2][tid] + whist[3][tid];
        atomicAdd(&g_cnt[n * NCLS + tid], c);
    }

    __threadfence();
    if (tid == 0) s_last = (atomicAdd(&g_done, 1u) == (unsigned)(gridDim.x - 1));
    __syncthreads();
    if (!s_last) return;

    // ---------------- epilogue (last CTA, reuses bin smem) ----------------
    struct Epi {
        float cnt[NB][NCLS];
        float mu[NB][NCLS][CH];
        float intra[NB][NCLS];
        float inter[NB];
        float nfg[NB];
        float l2i[NB];
    };
    Epi* e = reinterpret_cast<Epi*>(raw);
    __syncthreads();

    if (tid < NB * NCLS)
        e->cnt[tid / NCLS][tid % NCLS] = (float)g_cnt[tid];
    __syncthreads();

    {   // warp w = batch w: per-class mean + intra
        for (int k = 0; k < NCLS; ++k) {
            float cn = e->cnt[w][k];
            float s1 = __ldcg(&g_S1[w * NCLS * CH + k * CH + lane]);
            float s2 = __ldcg(&g_S2[w * NCLS * CH + k * CH + lane]);
            float m  = s1 / (cn + 1.0f);
            e->mu[w][k][lane] = m;
            float t2 = s2 + m * fmaf(cn, m, -2.0f * s1);
            #pragma unroll
            for (int o = 16; o; o >>= 1) t2 += __shfl_xor_sync(0xffffffffu, t2, o);
            if (lane == 0) e->intra[w][k] = t2 / ((float)CH * (cn + 1.0f));
        }
    }
    __syncthreads();

    // self-clean accumulators for the next graph replay (all reads done)
    for (int i = tid; i < NB * NCLS * CH; i += 128) { g_S1[i] = 0.f; g_S2[i] = 0.f; }
    if (tid < NB * NCLS) g_cnt[tid] = 0;
    if (tid == 0) g_done = 0u;

    if (tid < NB) {
        float nf = 0.f, li = 0.f;
        for (int k = 1; k < NCLS; ++k)
            if (e->cnt[tid][k] > 0.f) { nf += 1.f; li += e->intra[tid][k]; }
        e->nfg[tid] = nf;
        e->l2i[tid] = li / nf;
    }
    __syncthreads();

    {   // warp w = batch w: inter-class pairwise distances
        float acc = 0.f;
        for (int j = 1; j < NCLS; ++j) {
            if (e->cnt[w][j] <= 0.f) continue;
            float mj = e->mu[w][j][lane];
            for (int k = 1; k < NCLS; ++k) {
                if (e->cnt[w][k] > 0.f) {
                    float d = mj - e->mu[w][k][lane];
                    acc = fmaf(d, d, acc);
                }
            }
        }
        #pragma unroll
        for (int o = 16; o; o >>= 1) acc += __shfl_xor_sync(0xffffffffu, acc, o);
        if (lane == 0) e->inter[w] = acc / (float)CH;
    }
    __syncthreads();

    if (tid < NB)
        out[tid] = e->l2i[tid] - e->inter[tid] / (e->nfg[tid] * e->nfg[tid]);
}

// ---------------------------------------------------------------------------
extern "C" void kernel_launch(void* const* d_in, const int* in_sizes, int n_in,
                              void* d_out, int out_size) {
    const float* emb   = (const float*)d_in[0];   // (4,32,128,128) f32
    const int*   label = (const int*)d_in[1];     // (4,512,512) int32
    float*       out   = (float*)d_out;           // (4,) f32

    main_kernel<<<NB * 128 * 2, 128>>>(emb, label, out);
}